// round 1
// baseline (speedup 1.0000x reference)
#include <cuda_runtime.h>
#include <math.h>

// Problem constants
#define BATCH 8
#define NPTS 256
#define HD 128
#define BN (BATCH*NPTS)          // 2048 rows

// ---------------- scratch (device globals; no allocation allowed) ----------
__device__ float g_PA[BN*HD];    // h_i @ edg1_w[0:128]
__device__ float g_PB[BN*HD];    // h_j @ edg1_w[128:256]
__device__ float g_CA[BN*HD];    // h_i @ cor1_w[0:128]
__device__ float g_CB[BN*HD];    // h_j @ cor1_w[128:256]
__device__ float g_D2[BN*NPTS];  // |x_i - x_j|^2
__device__ float g_D02[BN*NPTS]; // |x0_i - x0_j|^2
__device__ float g_agg[BN*HD];   // mean_j e*m
__device__ float g_upd[BN*3];    // mean_j cw*shift*offdiag

__device__ __forceinline__ float sigm(float v) {
    return __fdividef(1.f, 1.f + __expf(-v));
}
__device__ __forceinline__ float siluf(float v) {
    return v * sigm(v);
}

// ---------------- kernel 1: per-node projections (TI=8 rows/block) ---------
__global__ void __launch_bounds__(128) proj_kernel(
    const float* __restrict__ h,
    const float* __restrict__ e1w,
    const float* __restrict__ c1w)
{
    const int r0 = blockIdx.x * 8;
    const int t  = threadIdx.x;
    __shared__ float hs[8][HD];
    #pragma unroll
    for (int r = 0; r < 8; r++) hs[r][t] = h[(r0 + r) * HD + t];
    __syncthreads();

    float pa[8], pb[8], ca[8], cb[8];
    #pragma unroll
    for (int r = 0; r < 8; r++) { pa[r]=0.f; pb[r]=0.f; ca[r]=0.f; cb[r]=0.f; }

    for (int k = 0; k < HD; k++) {
        float wea = e1w[k * HD + t];
        float web = e1w[(HD + k) * HD + t];
        float wca = c1w[k * HD + t];
        float wcb = c1w[(HD + k) * HD + t];
        #pragma unroll
        for (int r = 0; r < 8; r++) {
            float hk = hs[r][k];
            pa[r] = fmaf(hk, wea, pa[r]);
            pb[r] = fmaf(hk, web, pb[r]);
            ca[r] = fmaf(hk, wca, ca[r]);
            cb[r] = fmaf(hk, wcb, cb[r]);
        }
    }
    #pragma unroll
    for (int r = 0; r < 8; r++) {
        int bi = r0 + r;
        g_PA[bi * HD + t] = pa[r];
        g_PB[bi * HD + t] = pb[r];
        g_CA[bi * HD + t] = ca[r];
        g_CB[bi * HD + t] = cb[r];
    }
}

// ---------------- kernel 2: pairwise squared distances ---------------------
__global__ void __launch_bounds__(256) dist_kernel(
    const float* __restrict__ x, const float* __restrict__ x0)
{
    int idx = blockIdx.x * 256 + threadIdx.x;     // < BN*NPTS
    int j = idx & 255;
    int bi = idx >> 8;                            // b*256 + i
    int b  = bi >> 8;
    const float* xi = x  + bi * 3;
    const float* xj = x  + (b * NPTS + j) * 3;
    float dx = xi[0]-xj[0], dy = xi[1]-xj[1], dz = xi[2]-xj[2];
    g_D2[idx] = dx*dx + dy*dy + dz*dz;
    const float* yi = x0 + bi * 3;
    const float* yj = x0 + (b * NPTS + j) * 3;
    float ex = yi[0]-yj[0], ey = yi[1]-yj[1], ez = yi[2]-yj[2];
    g_D02[idx] = ex*ex + ey*ey + ez*ez;
}

// smem layout offsets (floats) shared by edge/cor kernels
#define OFF_W2   0
#define OFF_T1   16384
#define OFF_RED  18432
#define OFF_AUX  18496    // edge: es[16] | cor: (unused pad)
#define OFF_D2   18512
#define OFF_D02  18528
#define OFF_UPD  18544    // cor only: 48 floats
#define SMEM_EDGE_FLOATS 18544
#define SMEM_COR_FLOATS  18592

// ---------------- kernel 3: edge chain -> g_agg ----------------------------
__global__ void __launch_bounds__(128) edge_kernel(
    const float* __restrict__ e1w, const float* __restrict__ e1b,
    const float* __restrict__ e2w, const float* __restrict__ e2b,
    const float* __restrict__ eiw, const float* __restrict__ eib)
{
    extern __shared__ float sm[];
    float* W2s  = sm + OFF_W2;
    float* t1s  = sm + OFF_T1;
    float* red  = sm + OFF_RED;
    float* es   = sm + OFF_AUX;
    float* d2s  = sm + OFF_D2;
    float* d02s = sm + OFF_D02;

    const int bi = blockIdx.x;
    const int b  = bi >> 8;
    const int i  = bi & 255;
    const int t  = threadIdx.x;
    const int lane = t & 31, wrp = t >> 5;

    for (int idx = t; idx < HD * HD; idx += 128) W2s[idx] = e2w[idx];

    const float pak  = g_PA[bi * HD + t];
    const float w256 = e1w[256 * HD + t];
    const float w257 = e1w[257 * HD + t];
    const float b1   = e1b[t];
    const float b2   = e2b[t];
    const float wiv  = eiw[t];
    const float bi0  = eib[0];
    const float* PBb = g_PB + b * NPTS * HD;

    float aggA = 0.f;
    __syncthreads();

    for (int j0 = 0; j0 < NPTS; j0 += 16) {
        if (t < 16) {
            d2s[t]  = g_D2 [bi * NPTS + j0 + t];
            d02s[t] = g_D02[bi * NPTS + j0 + t];
        }
        __syncthreads();
        // producer: t1[jj][t]
        #pragma unroll
        for (int jj = 0; jj < 16; jj++) {
            float v = pak + PBb[(j0 + jj) * HD + t]
                    + d2s[jj] * w256 + d02s[jj] * w257 + b1;
            t1s[jj * HD + t] = siluf(v);
        }
        __syncthreads();
        // GEMM: acc[jj] = sum_k t1[jj][k] * W2[k][t]
        float acc[16];
        #pragma unroll
        for (int jj = 0; jj < 16; jj++) acc[jj] = 0.f;
        for (int k = 0; k < HD; k += 4) {
            float w0 = W2s[(k+0)*HD + t];
            float w1 = W2s[(k+1)*HD + t];
            float w2 = W2s[(k+2)*HD + t];
            float w3 = W2s[(k+3)*HD + t];
            #pragma unroll
            for (int jj = 0; jj < 16; jj++) {
                float4 tv = *reinterpret_cast<const float4*>(&t1s[jj * HD + k]);
                acc[jj] = fmaf(tv.x, w0, acc[jj]);
                acc[jj] = fmaf(tv.y, w1, acc[jj]);
                acc[jj] = fmaf(tv.z, w2, acc[jj]);
                acc[jj] = fmaf(tv.w, w3, acc[jj]);
            }
        }
        float m[16];
        #pragma unroll
        for (int jj = 0; jj < 16; jj++) m[jj] = siluf(acc[jj] + b2);
        // e[jj] = sigmoid(sum_o m*eiw + eib): warp reduce then cross-warp
        #pragma unroll
        for (int jj = 0; jj < 16; jj++) {
            float v = m[jj] * wiv;
            v += __shfl_xor_sync(0xffffffffu, v, 16);
            v += __shfl_xor_sync(0xffffffffu, v, 8);
            v += __shfl_xor_sync(0xffffffffu, v, 4);
            v += __shfl_xor_sync(0xffffffffu, v, 2);
            v += __shfl_xor_sync(0xffffffffu, v, 1);
            if (lane == 0) red[wrp * 16 + jj] = v;
        }
        __syncthreads();
        if (t < 16) {
            float s = red[t] + red[16 + t] + red[32 + t] + red[48 + t] + bi0;
            float e = sigm(s);
            if (j0 + t == i) e = 0.f;   // offdiag
            es[t] = e;
        }
        __syncthreads();
        #pragma unroll
        for (int jj = 0; jj < 16; jj++) aggA = fmaf(es[jj], m[jj], aggA);
        __syncthreads();
    }
    g_agg[bi * HD + t] = aggA * (1.0f / 256.0f);
}

// ---------------- kernel 4: coordinate chain -> g_upd ----------------------
__global__ void __launch_bounds__(128) cor_kernel(
    const float* __restrict__ c1w, const float* __restrict__ c1b,
    const float* __restrict__ c2w, const float* __restrict__ c2b,
    const float* __restrict__ c3w, const float* __restrict__ c3b,
    const float* __restrict__ x)
{
    extern __shared__ float sm[];
    float* W2s  = sm + OFF_W2;
    float* t1s  = sm + OFF_T1;
    float* red  = sm + OFF_RED;
    float* d2s  = sm + OFF_D2;
    float* d02s = sm + OFF_D02;
    float* updp = sm + OFF_UPD;

    const int bi = blockIdx.x;
    const int b  = bi >> 8;
    const int i  = bi & 255;
    const int t  = threadIdx.x;
    const int lane = t & 31, wrp = t >> 5;

    for (int idx = t; idx < HD * HD; idx += 128) W2s[idx] = c2w[idx];

    const float cak  = g_CA[bi * HD + t];
    const float w256 = c1w[256 * HD + t];
    const float w257 = c1w[257 * HD + t];
    const float b1   = c1b[t];
    const float b2   = c2b[t];
    const float w3v  = c3w[t];
    const float b3   = c3b[0];
    const float* CBb = g_CB + b * NPTS * HD;

    const float xi0 = x[bi * 3 + 0];
    const float xi1 = x[bi * 3 + 1];
    const float xi2 = x[bi * 3 + 2];
    float ux = 0.f, uy = 0.f, uz = 0.f;

    __syncthreads();

    for (int j0 = 0; j0 < NPTS; j0 += 16) {
        if (t < 16) {
            d2s[t]  = g_D2 [bi * NPTS + j0 + t];
            d02s[t] = g_D02[bi * NPTS + j0 + t];
        }
        __syncthreads();
        #pragma unroll
        for (int jj = 0; jj < 16; jj++) {
            float v = cak + CBb[(j0 + jj) * HD + t]
                    + d2s[jj] * w256 + d02s[jj] * w257 + b1;
            t1s[jj * HD + t] = siluf(v);
        }
        __syncthreads();
        float acc[16];
        #pragma unroll
        for (int jj = 0; jj < 16; jj++) acc[jj] = 0.f;
        for (int k = 0; k < HD; k += 4) {
            float w0 = W2s[(k+0)*HD + t];
            float w1 = W2s[(k+1)*HD + t];
            float w2 = W2s[(k+2)*HD + t];
            float w3 = W2s[(k+3)*HD + t];
            #pragma unroll
            for (int jj = 0; jj < 16; jj++) {
                float4 tv = *reinterpret_cast<const float4*>(&t1s[jj * HD + k]);
                acc[jj] = fmaf(tv.x, w0, acc[jj]);
                acc[jj] = fmaf(tv.y, w1, acc[jj]);
                acc[jj] = fmaf(tv.z, w2, acc[jj]);
                acc[jj] = fmaf(tv.w, w3, acc[jj]);
            }
        }
        #pragma unroll
        for (int jj = 0; jj < 16; jj++) {
            float c2v = siluf(acc[jj] + b2);
            float v = c2v * w3v;
            v += __shfl_xor_sync(0xffffffffu, v, 16);
            v += __shfl_xor_sync(0xffffffffu, v, 8);
            v += __shfl_xor_sync(0xffffffffu, v, 4);
            v += __shfl_xor_sync(0xffffffffu, v, 2);
            v += __shfl_xor_sync(0xffffffffu, v, 1);
            if (lane == 0) red[wrp * 16 + jj] = v;
        }
        __syncthreads();
        if (t < 16) {
            int j = j0 + t;
            float cw = red[t] + red[16 + t] + red[32 + t] + red[48 + t] + b3;
            if (j != i) {
                float d2v  = d2s[t];
                float dist = (d2v > 0.f) ? sqrtf(d2v) : 0.f;
                float f = __fdividef(cw, dist + 1.f);
                const float* xj = x + (b * NPTS + j) * 3;
                ux = fmaf(f, xi0 - xj[0], ux);
                uy = fmaf(f, xi1 - xj[1], uy);
                uz = fmaf(f, xi2 - xj[2], uz);
            }
        }
        __syncthreads();
    }
    if (t < 16) { updp[t*3+0] = ux; updp[t*3+1] = uy; updp[t*3+2] = uz; }
    __syncthreads();
    if (t < 3) {
        float s = 0.f;
        #pragma unroll
        for (int r = 0; r < 16; r++) s += updp[r * 3 + t];
        g_upd[bi * 3 + t] = s * (1.0f / 256.0f);
    }
}

// ---------------- kernel 5: node MLP + outputs (TI=8 rows/block) -----------
__global__ void __launch_bounds__(128) final_kernel(
    const float* __restrict__ hin, const float* __restrict__ xin,
    const float* __restrict__ pm,
    const float* __restrict__ n1w, const float* __restrict__ n1b,
    const float* __restrict__ n2w, const float* __restrict__ n2b,
    float* __restrict__ out)
{
    const int r0 = blockIdx.x * 8;
    const int t  = threadIdx.x;
    __shared__ float nin[8][256];
    __shared__ float tmid[8][HD];
    #pragma unroll
    for (int r = 0; r < 8; r++) {
        nin[r][t]       = hin[(r0 + r) * HD + t];
        nin[r][HD + t]  = g_agg[(r0 + r) * HD + t];
    }
    __syncthreads();
    float a[8];
    #pragma unroll
    for (int r = 0; r < 8; r++) a[r] = n1b[t];
    for (int k = 0; k < 256; k++) {
        float wv = n1w[k * HD + t];
        #pragma unroll
        for (int r = 0; r < 8; r++) a[r] = fmaf(nin[r][k], wv, a[r]);
    }
    #pragma unroll
    for (int r = 0; r < 8; r++) tmid[r][t] = siluf(a[r]);
    __syncthreads();
    #pragma unroll
    for (int r = 0; r < 8; r++) a[r] = n2b[t];
    for (int k = 0; k < HD; k++) {
        float wv = n2w[k * HD + t];
        #pragma unroll
        for (int r = 0; r < 8; r++) a[r] = fmaf(tmid[r][k], wv, a[r]);
    }
    float* outx = out;                  // x_next: BN*3
    float* outh = out + BN * 3;         // h_next: BN*HD
    #pragma unroll
    for (int r = 0; r < 8; r++) {
        int bi = r0 + r;
        float mask = pm[bi];
        outh[bi * HD + t] = (nin[r][t] + a[r]) * mask;
        if (t < 3) outx[bi * 3 + t] = (xin[bi * 3 + t] + g_upd[bi * 3 + t]) * mask;
    }
}

// ---------------- launch ----------------------------------------------------
extern "C" void kernel_launch(void* const* d_in, const int* in_sizes, int n_in,
                              void* d_out, int out_size)
{
    const float* x   = (const float*)d_in[0];
    const float* h   = (const float*)d_in[1];
    const float* x0  = (const float*)d_in[2];
    const float* pm  = (const float*)d_in[3];
    const float* e1w = (const float*)d_in[4];
    const float* e1b = (const float*)d_in[5];
    const float* e2w = (const float*)d_in[6];
    const float* e2b = (const float*)d_in[7];
    const float* eiw = (const float*)d_in[8];
    const float* eib = (const float*)d_in[9];
    const float* n1w = (const float*)d_in[10];
    const float* n1b = (const float*)d_in[11];
    const float* n2w = (const float*)d_in[12];
    const float* n2b = (const float*)d_in[13];
    const float* c1w = (const float*)d_in[14];
    const float* c1b = (const float*)d_in[15];
    const float* c2w = (const float*)d_in[16];
    const float* c2b = (const float*)d_in[17];
    const float* c3w = (const float*)d_in[18];
    const float* c3b = (const float*)d_in[19];
    float* out = (float*)d_out;

    const size_t smemE = SMEM_EDGE_FLOATS * sizeof(float);
    const size_t smemC = SMEM_COR_FLOATS  * sizeof(float);
    cudaFuncSetAttribute(edge_kernel, cudaFuncAttributeMaxDynamicSharedMemorySize, (int)smemE);
    cudaFuncSetAttribute(cor_kernel,  cudaFuncAttributeMaxDynamicSharedMemorySize, (int)smemC);

    proj_kernel<<<BN / 8, 128>>>(h, e1w, c1w);
    dist_kernel<<<(BN * NPTS) / 256, 256>>>(x, x0);
    edge_kernel<<<BN, 128, smemE>>>(e1w, e1b, e2w, e2b, eiw, eib);
    cor_kernel<<<BN, 128, smemC>>>(c1w, c1b, c2w, c2b, c3w, c3b, x);
    final_kernel<<<BN / 8, 128>>>(h, x, pm, n1w, n1b, n2w, n2b, out);
}

// round 2
// speedup vs baseline: 1.1733x; 1.1733x over previous
#include <cuda_runtime.h>
#include <math.h>

// Problem constants
#define BATCH 8
#define NPTS 256
#define HD 128
#define BN (BATCH*NPTS)          // 2048 rows

// ---------------- scratch (device globals; no allocation allowed) ----------
__device__ float g_PA[BN*HD];    // h_i @ edg1_w[0:128]
__device__ float g_PB[BN*HD];    // h_j @ edg1_w[128:256]
__device__ float g_CA[BN*HD];    // h_i @ cor1_w[0:128]
__device__ float g_CB[BN*HD];    // h_j @ cor1_w[128:256]
__device__ float g_D2[BN*NPTS];  // |x_i - x_j|^2
__device__ float g_D02[BN*NPTS]; // |x0_i - x0_j|^2
__device__ float g_agg[BN*HD];   // mean_j e*m
__device__ float g_upd[BN*3];    // mean_j cw*shift*offdiag

__device__ __forceinline__ float sigm(float v) {
    return __fdividef(1.f, 1.f + __expf(-v));
}
__device__ __forceinline__ float siluf(float v) {
    return v * sigm(v);
}

// ---------------- kernel 1: per-node projections (TI=8 rows/block) ---------
__global__ void __launch_bounds__(128) proj_kernel(
    const float* __restrict__ h,
    const float* __restrict__ e1w,
    const float* __restrict__ c1w)
{
    const int r0 = blockIdx.x * 8;
    const int t  = threadIdx.x;
    __shared__ float hs[8][HD];
    #pragma unroll
    for (int r = 0; r < 8; r++) hs[r][t] = h[(r0 + r) * HD + t];
    __syncthreads();

    float pa[8], pb[8], ca[8], cb[8];
    #pragma unroll
    for (int r = 0; r < 8; r++) { pa[r]=0.f; pb[r]=0.f; ca[r]=0.f; cb[r]=0.f; }

    for (int k = 0; k < HD; k++) {
        float wea = e1w[k * HD + t];
        float web = e1w[(HD + k) * HD + t];
        float wca = c1w[k * HD + t];
        float wcb = c1w[(HD + k) * HD + t];
        #pragma unroll
        for (int r = 0; r < 8; r++) {
            float hk = hs[r][k];
            pa[r] = fmaf(hk, wea, pa[r]);
            pb[r] = fmaf(hk, web, pb[r]);
            ca[r] = fmaf(hk, wca, ca[r]);
            cb[r] = fmaf(hk, wcb, cb[r]);
        }
    }
    #pragma unroll
    for (int r = 0; r < 8; r++) {
        int bi = r0 + r;
        g_PA[bi * HD + t] = pa[r];
        g_PB[bi * HD + t] = pb[r];
        g_CA[bi * HD + t] = ca[r];
        g_CB[bi * HD + t] = cb[r];
    }
}

// ---------------- kernel 2: pairwise squared distances ---------------------
__global__ void __launch_bounds__(256) dist_kernel(
    const float* __restrict__ x, const float* __restrict__ x0)
{
    int idx = blockIdx.x * 256 + threadIdx.x;     // < BN*NPTS
    int j = idx & 255;
    int bi = idx >> 8;                            // b*256 + i
    int b  = bi >> 8;
    const float* xi = x  + bi * 3;
    const float* xj = x  + (b * NPTS + j) * 3;
    float dx = xi[0]-xj[0], dy = xi[1]-xj[1], dz = xi[2]-xj[2];
    g_D2[idx] = dx*dx + dy*dy + dz*dz;
    const float* yi = x0 + bi * 3;
    const float* yj = x0 + (b * NPTS + j) * 3;
    float ex = yi[0]-yj[0], ey = yi[1]-yj[1], ez = yi[2]-yj[2];
    g_D02[idx] = ex*ex + ey*ey + ez*ez;
}

// ---------------- kernel 3: edge chain -> g_agg ----------------------------
// W2 stays in L1 (read via LDG, shared by all blocks). smem only holds the
// 16x128 t1 tile + small reduction buffers -> 8 blocks/SM (50% occupancy).
__global__ void __launch_bounds__(128, 8) edge_kernel(
    const float* __restrict__ e1w, const float* __restrict__ e1b,
    const float* __restrict__ e2w, const float* __restrict__ e2b,
    const float* __restrict__ eiw, const float* __restrict__ eib)
{
    __shared__ float t1s[16 * HD];
    __shared__ float red[64];
    __shared__ float es[16];
    __shared__ float d2s[16];
    __shared__ float d02s[16];

    const int bi = blockIdx.x;
    const int b  = bi >> 8;
    const int i  = bi & 255;
    const int t  = threadIdx.x;
    const int lane = t & 31, wrp = t >> 5;

    const float pak  = g_PA[bi * HD + t];
    const float w256 = e1w[256 * HD + t];
    const float w257 = e1w[257 * HD + t];
    const float b1   = e1b[t];
    const float b2   = e2b[t];
    const float wiv  = eiw[t];
    const float bi0  = eib[0];
    const float* PBb = g_PB + b * NPTS * HD;

    float aggA = 0.f;

    for (int j0 = 0; j0 < NPTS; j0 += 16) {
        if (t < 16) {
            d2s[t]  = g_D2 [bi * NPTS + j0 + t];
            d02s[t] = g_D02[bi * NPTS + j0 + t];
        }
        __syncthreads();
        // producer: t1[jj][t]
        #pragma unroll
        for (int jj = 0; jj < 16; jj++) {
            float v = pak + __ldg(&PBb[(j0 + jj) * HD + t])
                    + d2s[jj] * w256 + d02s[jj] * w257 + b1;
            t1s[jj * HD + t] = siluf(v);
        }
        __syncthreads();
        // GEMM: acc[jj] = sum_k t1[jj][k] * W2[k][t]
        float acc[16];
        #pragma unroll
        for (int jj = 0; jj < 16; jj++) acc[jj] = 0.f;
        #pragma unroll 4
        for (int k = 0; k < HD; k += 4) {
            float w0 = __ldg(&e2w[(k+0)*HD + t]);
            float w1 = __ldg(&e2w[(k+1)*HD + t]);
            float w2 = __ldg(&e2w[(k+2)*HD + t]);
            float w3 = __ldg(&e2w[(k+3)*HD + t]);
            #pragma unroll
            for (int jj = 0; jj < 16; jj++) {
                float4 tv = *reinterpret_cast<const float4*>(&t1s[jj * HD + k]);
                acc[jj] = fmaf(tv.x, w0, acc[jj]);
                acc[jj] = fmaf(tv.y, w1, acc[jj]);
                acc[jj] = fmaf(tv.z, w2, acc[jj]);
                acc[jj] = fmaf(tv.w, w3, acc[jj]);
            }
        }
        float m[16];
        #pragma unroll
        for (int jj = 0; jj < 16; jj++) m[jj] = siluf(acc[jj] + b2);
        // e[jj] = sigmoid(sum_o m*eiw + eib): warp reduce then cross-warp
        #pragma unroll
        for (int jj = 0; jj < 16; jj++) {
            float v = m[jj] * wiv;
            v += __shfl_xor_sync(0xffffffffu, v, 16);
            v += __shfl_xor_sync(0xffffffffu, v, 8);
            v += __shfl_xor_sync(0xffffffffu, v, 4);
            v += __shfl_xor_sync(0xffffffffu, v, 2);
            v += __shfl_xor_sync(0xffffffffu, v, 1);
            if (lane == 0) red[wrp * 16 + jj] = v;
        }
        __syncthreads();
        if (t < 16) {
            float s = red[t] + red[16 + t] + red[32 + t] + red[48 + t] + bi0;
            float e = sigm(s);
            if (j0 + t == i) e = 0.f;   // offdiag
            es[t] = e;
        }
        __syncthreads();
        #pragma unroll
        for (int jj = 0; jj < 16; jj++) aggA = fmaf(es[jj], m[jj], aggA);
        __syncthreads();
    }
    g_agg[bi * HD + t] = aggA * (1.0f / 256.0f);
}

// ---------------- kernel 4: coordinate chain -> g_upd ----------------------
__global__ void __launch_bounds__(128, 8) cor_kernel(
    const float* __restrict__ c1w, const float* __restrict__ c1b,
    const float* __restrict__ c2w, const float* __restrict__ c2b,
    const float* __restrict__ c3w, const float* __restrict__ c3b,
    const float* __restrict__ x)
{
    __shared__ float t1s[16 * HD];
    __shared__ float red[64];
    __shared__ float d2s[16];
    __shared__ float d02s[16];
    __shared__ float updp[48];

    const int bi = blockIdx.x;
    const int b  = bi >> 8;
    const int i  = bi & 255;
    const int t  = threadIdx.x;
    const int lane = t & 31, wrp = t >> 5;

    const float cak  = g_CA[bi * HD + t];
    const float w256 = c1w[256 * HD + t];
    const float w257 = c1w[257 * HD + t];
    const float b1   = c1b[t];
    const float b2   = c2b[t];
    const float w3v  = c3w[t];
    const float b3   = c3b[0];
    const float* CBb = g_CB + b * NPTS * HD;

    const float xi0 = x[bi * 3 + 0];
    const float xi1 = x[bi * 3 + 1];
    const float xi2 = x[bi * 3 + 2];
    float ux = 0.f, uy = 0.f, uz = 0.f;

    for (int j0 = 0; j0 < NPTS; j0 += 16) {
        if (t < 16) {
            d2s[t]  = g_D2 [bi * NPTS + j0 + t];
            d02s[t] = g_D02[bi * NPTS + j0 + t];
        }
        __syncthreads();
        #pragma unroll
        for (int jj = 0; jj < 16; jj++) {
            float v = cak + __ldg(&CBb[(j0 + jj) * HD + t])
                    + d2s[jj] * w256 + d02s[jj] * w257 + b1;
            t1s[jj * HD + t] = siluf(v);
        }
        __syncthreads();
        float acc[16];
        #pragma unroll
        for (int jj = 0; jj < 16; jj++) acc[jj] = 0.f;
        #pragma unroll 4
        for (int k = 0; k < HD; k += 4) {
            float w0 = __ldg(&c2w[(k+0)*HD + t]);
            float w1 = __ldg(&c2w[(k+1)*HD + t]);
            float w2 = __ldg(&c2w[(k+2)*HD + t]);
            float w3 = __ldg(&c2w[(k+3)*HD + t]);
            #pragma unroll
            for (int jj = 0; jj < 16; jj++) {
                float4 tv = *reinterpret_cast<const float4*>(&t1s[jj * HD + k]);
                acc[jj] = fmaf(tv.x, w0, acc[jj]);
                acc[jj] = fmaf(tv.y, w1, acc[jj]);
                acc[jj] = fmaf(tv.z, w2, acc[jj]);
                acc[jj] = fmaf(tv.w, w3, acc[jj]);
            }
        }
        #pragma unroll
        for (int jj = 0; jj < 16; jj++) {
            float c2v = siluf(acc[jj] + b2);
            float v = c2v * w3v;
            v += __shfl_xor_sync(0xffffffffu, v, 16);
            v += __shfl_xor_sync(0xffffffffu, v, 8);
            v += __shfl_xor_sync(0xffffffffu, v, 4);
            v += __shfl_xor_sync(0xffffffffu, v, 2);
            v += __shfl_xor_sync(0xffffffffu, v, 1);
            if (lane == 0) red[wrp * 16 + jj] = v;
        }
        __syncthreads();
        if (t < 16) {
            int j = j0 + t;
            float cw = red[t] + red[16 + t] + red[32 + t] + red[48 + t] + b3;
            if (j != i) {
                float d2v  = d2s[t];
                float dist = (d2v > 0.f) ? sqrtf(d2v) : 0.f;
                float f = __fdividef(cw, dist + 1.f);
                const float* xj = x + (b * NPTS + j) * 3;
                ux = fmaf(f, xi0 - xj[0], ux);
                uy = fmaf(f, xi1 - xj[1], uy);
                uz = fmaf(f, xi2 - xj[2], uz);
            }
        }
        __syncthreads();
    }
    if (t < 16) { updp[t*3+0] = ux; updp[t*3+1] = uy; updp[t*3+2] = uz; }
    __syncthreads();
    if (t < 3) {
        float s = 0.f;
        #pragma unroll
        for (int r = 0; r < 16; r++) s += updp[r * 3 + t];
        g_upd[bi * 3 + t] = s * (1.0f / 256.0f);
    }
}

// ---------------- kernel 5: node MLP + outputs (TI=8 rows/block) -----------
__global__ void __launch_bounds__(128) final_kernel(
    const float* __restrict__ hin, const float* __restrict__ xin,
    const float* __restrict__ pm,
    const float* __restrict__ n1w, const float* __restrict__ n1b,
    const float* __restrict__ n2w, const float* __restrict__ n2b,
    float* __restrict__ out)
{
    const int r0 = blockIdx.x * 8;
    const int t  = threadIdx.x;
    __shared__ float nin[8][256];
    __shared__ float tmid[8][HD];
    #pragma unroll
    for (int r = 0; r < 8; r++) {
        nin[r][t]       = hin[(r0 + r) * HD + t];
        nin[r][HD + t]  = g_agg[(r0 + r) * HD + t];
    }
    __syncthreads();
    float a[8];
    #pragma unroll
    for (int r = 0; r < 8; r++) a[r] = n1b[t];
    for (int k = 0; k < 256; k++) {
        float wv = n1w[k * HD + t];
        #pragma unroll
        for (int r = 0; r < 8; r++) a[r] = fmaf(nin[r][k], wv, a[r]);
    }
    #pragma unroll
    for (int r = 0; r < 8; r++) tmid[r][t] = siluf(a[r]);
    __syncthreads();
    #pragma unroll
    for (int r = 0; r < 8; r++) a[r] = n2b[t];
    for (int k = 0; k < HD; k++) {
        float wv = n2w[k * HD + t];
        #pragma unroll
        for (int r = 0; r < 8; r++) a[r] = fmaf(tmid[r][k], wv, a[r]);
    }
    float* outx = out;                  // x_next: BN*3
    float* outh = out + BN * 3;         // h_next: BN*HD
    #pragma unroll
    for (int r = 0; r < 8; r++) {
        int bi = r0 + r;
        float mask = pm[bi];
        outh[bi * HD + t] = (nin[r][t] + a[r]) * mask;
        if (t < 3) outx[bi * 3 + t] = (xin[bi * 3 + t] + g_upd[bi * 3 + t]) * mask;
    }
}

// ---------------- launch ----------------------------------------------------
extern "C" void kernel_launch(void* const* d_in, const int* in_sizes, int n_in,
                              void* d_out, int out_size)
{
    const float* x   = (const float*)d_in[0];
    const float* h   = (const float*)d_in[1];
    const float* x0  = (const float*)d_in[2];
    const float* pm  = (const float*)d_in[3];
    const float* e1w = (const float*)d_in[4];
    const float* e1b = (const float*)d_in[5];
    const float* e2w = (const float*)d_in[6];
    const float* e2b = (const float*)d_in[7];
    const float* eiw = (const float*)d_in[8];
    const float* eib = (const float*)d_in[9];
    const float* n1w = (const float*)d_in[10];
    const float* n1b = (const float*)d_in[11];
    const float* n2w = (const float*)d_in[12];
    const float* n2b = (const float*)d_in[13];
    const float* c1w = (const float*)d_in[14];
    const float* c1b = (const float*)d_in[15];
    const float* c2w = (const float*)d_in[16];
    const float* c2b = (const float*)d_in[17];
    const float* c3w = (const float*)d_in[18];
    const float* c3b = (const float*)d_in[19];
    float* out = (float*)d_out;

    proj_kernel<<<BN / 8, 128>>>(h, e1w, c1w);
    dist_kernel<<<(BN * NPTS) / 256, 256>>>(x, x0);
    edge_kernel<<<BN, 128>>>(e1w, e1b, e2w, e2b, eiw, eib);
    cor_kernel<<<BN, 128>>>(c1w, c1b, c2w, c2b, c3w, c3b, x);
    final_kernel<<<BN / 8, 128>>>(h, x, pm, n1w, n1b, n2w, n2b, out);
}